// round 1
// baseline (speedup 1.0000x reference)
#include <cuda_runtime.h>
#include <cuda_bf16.h>
#include <stdint.h>

// Problem constants
#define N_NODES 30000
#define N_EDGES 480000
#define K_SUB   32
#define P_PAIRS 16384
#define IN_DIM  1024
#define H_DIM   512
#define Z_DIM   128
#define BN_DIM  8
#define DB_DIM  16
#define DEC0_DIM 144   // Z + DB

// ---------------- scratch (static device globals; no allocation) -------------
__device__ float g_bufA[(size_t)N_NODES * H_DIM];
__device__ float g_bufB[(size_t)N_NODES * H_DIM];
__device__ float g_bufC[(size_t)N_NODES * H_DIM];
__device__ float g_bufD[(size_t)N_NODES * Z_DIM];
__device__ float g_bufE[(size_t)N_NODES * Z_DIM];
__device__ float g_zn  [(size_t)N_NODES * Z_DIM];   // z_node (x path)
__device__ float g_zn2 [(size_t)N_NODES * Z_DIM];   // z_node (shuffled path)
__device__ float g_be  [(size_t)N_NODES * DB_DIM];
__device__ float g_znb [(size_t)N_NODES * DEC0_DIM];
__device__ float g_aggd[(size_t)N_NODES * DEC0_DIM];

// ---------------- SGEMM: C[M,N] = (A [+A2]) @ B [+bias] ----------------------
// A row-major [M,K], B row-major [K,N]. Requires K%8==0, N%128==0, rows 16B-aligned.
#define BM 128
#define BNT 128
#define BK 8
#define TM 8
#define TN 8

__global__ __launch_bounds__(256)
void sgemm_kernel(int M, int Nn, int K,
                  const float* __restrict__ A, const float* __restrict__ A2,
                  const float* __restrict__ B, const float* __restrict__ bias,
                  float* __restrict__ C)
{
    __shared__ float As[BK][BM];
    __shared__ float Bs[BK][BNT];

    const int bx = blockIdx.x;      // N tile
    const int by = blockIdx.y;      // M tile
    const int tid = threadIdx.x;    // 256

    const int rowA = tid >> 1;              // 0..127
    const int colA = (tid & 1) * 4;         // 0 or 4
    const int rowB = tid >> 5;              // 0..7
    const int colB = (tid & 31) * 4;        // 0..124

    const int tRow = (tid >> 4) * TM;       // 0..120
    const int tCol = (tid & 15) * TN;       // 0..120

    const int mBase = by * BM;
    const int nBase = bx * BNT;

    float acc[TM][TN];
    #pragma unroll
    for (int i = 0; i < TM; i++)
        #pragma unroll
        for (int j = 0; j < TN; j++) acc[i][j] = 0.f;

    for (int k0 = 0; k0 < K; k0 += BK) {
        // load A tile (with optional A2 add), transposed into As
        int m = mBase + rowA;
        float4 av = make_float4(0.f, 0.f, 0.f, 0.f);
        if (m < M) {
            av = *(const float4*)(A + (size_t)m * K + k0 + colA);
            if (A2) {
                float4 a2 = *(const float4*)(A2 + (size_t)m * K + k0 + colA);
                av.x += a2.x; av.y += a2.y; av.z += a2.z; av.w += a2.w;
            }
        }
        As[colA + 0][rowA] = av.x;
        As[colA + 1][rowA] = av.y;
        As[colA + 2][rowA] = av.z;
        As[colA + 3][rowA] = av.w;

        // load B tile
        float4 bv = *(const float4*)(B + (size_t)(k0 + rowB) * Nn + nBase + colB);
        *(float4*)&Bs[rowB][colB] = bv;

        __syncthreads();

        #pragma unroll
        for (int kk = 0; kk < BK; kk++) {
            float ra[TM], rb[TN];
            #pragma unroll
            for (int i = 0; i < TM; i++) ra[i] = As[kk][tRow + i];
            #pragma unroll
            for (int j = 0; j < TN; j++) rb[j] = Bs[kk][tCol + j];
            #pragma unroll
            for (int i = 0; i < TM; i++)
                #pragma unroll
                for (int j = 0; j < TN; j++)
                    acc[i][j] += ra[i] * rb[j];
        }
        __syncthreads();
    }

    // store
    #pragma unroll
    for (int i = 0; i < TM; i++) {
        int m = mBase + tRow + i;
        if (m >= M) break;
        #pragma unroll
        for (int j = 0; j < TN; j += 4) {
            int n = nBase + tCol + j;
            float4 v = make_float4(acc[i][j], acc[i][j+1], acc[i][j+2], acc[i][j+3]);
            if (bias) {
                v.x += bias[n]; v.y += bias[n+1]; v.z += bias[n+2]; v.w += bias[n+3];
            }
            *(float4*)(C + (size_t)m * Nn + n) = v;
        }
    }
}

// ---------------- edge aggregation: out[dst] += X[src] -----------------------
template<int D>
__global__ void agg_kernel(const float* __restrict__ X, float* __restrict__ out,
                           const int* __restrict__ src, const int* __restrict__ dst,
                           int E)
{
    constexpr int D4 = D / 4;
    long long idx = (long long)blockIdx.x * blockDim.x + threadIdx.x;
    if (idx >= (long long)E * D4) return;
    int e = (int)(idx / D4);
    int c = (int)(idx % D4) * 4;
    int s = __ldg(&src[e]);
    int d = __ldg(&dst[e]);
    float4 v = *(const float4*)(X + (size_t)s * D + c);
    float* o = out + (size_t)d * D + c;
    atomicAdd(o + 0, v.x);
    atomicAdd(o + 1, v.y);
    atomicAdd(o + 2, v.z);
    atomicAdd(o + 3, v.w);
}

// ---------------- fused (Y [+AGG] + bias) -> LayerNorm -> ReLU ---------------
template<int D>
__global__ void ln_relu_kernel(const float* __restrict__ Y, const float* __restrict__ AGG,
                               const float* __restrict__ bias, float* __restrict__ out,
                               int Nrows)
{
    constexpr int V = D / 128;  // float4 per lane
    int w = (int)((blockIdx.x * (long long)blockDim.x + threadIdx.x) >> 5);
    if (w >= Nrows) return;
    int lane = threadIdx.x & 31;

    float4 v[V];
    float s = 0.f, sq = 0.f;
    #pragma unroll
    for (int i = 0; i < V; i++) {
        int c = (lane + i * 32) * 4;
        float4 y = *(const float4*)(Y + (size_t)w * D + c);
        if (AGG) {
            float4 a = *(const float4*)(AGG + (size_t)w * D + c);
            y.x += a.x; y.y += a.y; y.z += a.z; y.w += a.w;
        }
        float4 b = *(const float4*)(bias + c);
        y.x += b.x; y.y += b.y; y.z += b.z; y.w += b.w;
        v[i] = y;
        s  += y.x + y.y + y.z + y.w;
        sq += y.x*y.x + y.y*y.y + y.z*y.z + y.w*y.w;
    }
    #pragma unroll
    for (int off = 16; off; off >>= 1) {
        s  += __shfl_xor_sync(0xffffffffu, s,  off);
        sq += __shfl_xor_sync(0xffffffffu, sq, off);
    }
    float mean = s / D;
    float var  = sq / D - mean * mean;
    float inv  = rsqrtf(var + 1e-5f);
    #pragma unroll
    for (int i = 0; i < V; i++) {
        int c = (lane + i * 32) * 4;
        float4 y = v[i];
        y.x = fmaxf((y.x - mean) * inv, 0.f);
        y.y = fmaxf((y.y - mean) * inv, 0.f);
        y.z = fmaxf((y.z - mean) * inv, 0.f);
        y.w = fmaxf((y.w - mean) * inv, 0.f);
        *(float4*)(out + (size_t)w * D + c) = y;
    }
}

// ---------------- subgraph mean pool (K=32, Z=128): warp per node ------------
__global__ void pool_kernel(const float* __restrict__ zn, const int* __restrict__ idx,
                            float* __restrict__ out, int Nrows)
{
    int w = (int)((blockIdx.x * (long long)blockDim.x + threadIdx.x) >> 5);
    if (w >= Nrows) return;
    int lane = threadIdx.x & 31;
    int myidx = __ldg(&idx[(size_t)w * 32 + lane]);
    float4 acc = make_float4(0.f, 0.f, 0.f, 0.f);
    #pragma unroll
    for (int k = 0; k < 32; k++) {
        int j = __shfl_sync(0xffffffffu, myidx, k);
        float4 v = *(const float4*)(zn + (size_t)j * 128 + lane * 4);
        acc.x += v.x; acc.y += v.y; acc.z += v.z; acc.w += v.w;
    }
    const float inv = 1.f / 32.f;
    acc.x *= inv; acc.y *= inv; acc.z *= inv; acc.w *= inv;
    *(float4*)(out + (size_t)w * 128 + lane * 4) = acc;
}

// ---------------- batch encoder MLP (8 -> 12 relu -> 16) ---------------------
__global__ void be_kernel(const float* __restrict__ bl,
                          const float* __restrict__ W0, const float* __restrict__ b0,
                          const float* __restrict__ W1, const float* __restrict__ b1,
                          float* __restrict__ out, int Nr)
{
    int n = blockIdx.x * blockDim.x + threadIdx.x;
    if (n >= Nr) return;
    float in[8];
    #pragma unroll
    for (int i = 0; i < 8; i++) in[i] = bl[(size_t)n * 8 + i];
    float h[12];
    #pragma unroll
    for (int j = 0; j < 12; j++) {
        float s = b0[j];
        #pragma unroll
        for (int i = 0; i < 8; i++) s += in[i] * W0[i * 12 + j];
        h[j] = fmaxf(s, 0.f);
    }
    #pragma unroll
    for (int j = 0; j < 16; j++) {
        float s = b1[j];
        #pragma unroll
        for (int i = 0; i < 12; i++) s += h[i] * W1[i * 16 + j];
        out[(size_t)n * 16 + j] = s;
    }
}

// ---------------- batch discriminator (z_sub: 128 -> 64 relu -> 8) -----------
__global__ void bd_kernel(const float* __restrict__ zs,
                          const float* __restrict__ W0, const float* __restrict__ b0,
                          const float* __restrict__ W1, const float* __restrict__ b1,
                          float* __restrict__ out)
{
    int n = blockIdx.x;
    int t = threadIdx.x;  // 64
    __shared__ float z[128];
    __shared__ float h[64];
    z[t]      = zs[(size_t)n * 128 + t];
    z[64 + t] = zs[(size_t)n * 128 + 64 + t];
    __syncthreads();
    float s = b0[t];
    #pragma unroll 8
    for (int d = 0; d < 128; d++) s += z[d] * W0[d * 64 + t];
    h[t] = fmaxf(s, 0.f);
    __syncthreads();
    if (t < 8) {
        float o = b1[t];
        #pragma unroll 8
        for (int k = 0; k < 64; k++) o += h[k] * W1[k * 8 + t];
        out[(size_t)n * 8 + t] = o;
    }
}

// ---------------- bilinear discriminator -------------------------------------
__global__ void bil_kernel(const float* __restrict__ zs, const float* __restrict__ zss,
                           const float* __restrict__ W,
                           const int* __restrict__ pos, const int* __restrict__ neg,
                           float* __restrict__ lp, float* __restrict__ ln_)
{
    int p = blockIdx.x;
    int t = threadIdx.x;  // 128
    __shared__ float zp[128];
    __shared__ float red[8];
    int pi = __ldg(&pos[p]);
    int ni = __ldg(&neg[p]);
    zp[t] = zs[(size_t)pi * 128 + t];
    __syncthreads();
    float acc = 0.f;
    #pragma unroll 8
    for (int d = 0; d < 128; d++) acc += zp[d] * W[d * 128 + t];
    float sp = acc * zss[(size_t)pi * 128 + t];
    float sn = acc * zss[(size_t)ni * 128 + t];
    #pragma unroll
    for (int off = 16; off; off >>= 1) {
        sp += __shfl_xor_sync(0xffffffffu, sp, off);
        sn += __shfl_xor_sync(0xffffffffu, sn, off);
    }
    if ((t & 31) == 0) { red[t >> 5] = sp; red[4 + (t >> 5)] = sn; }
    __syncthreads();
    if (t == 0) lp[p]  = red[0] + red[1] + red[2] + red[3];
    if (t == 1) ln_[p] = red[4] + red[5] + red[6] + red[7];
}

// ---------------- concat z_node | batch_emb -> [N, 144] ----------------------
__global__ void concat_kernel(const float* __restrict__ zn, const float* __restrict__ be,
                              float* __restrict__ znb, int Nr)
{
    int idx = blockIdx.x * blockDim.x + threadIdx.x;
    if (idx >= Nr * DEC0_DIM) return;
    int n = idx / DEC0_DIM, c = idx - n * DEC0_DIM;
    znb[idx] = (c < Z_DIM) ? zn[(size_t)n * Z_DIM + c]
                           : be[(size_t)n * DB_DIM + (c - Z_DIM)];
}

// =============================================================================
extern "C" void kernel_launch(void* const* d_in, const int* in_sizes, int n_in,
                              void* d_out, int out_size)
{
    const float* x      = (const float*)d_in[0];
    const float* x_shf  = (const float*)d_in[1];
    const float* bl     = (const float*)d_in[2];
    const float* enc_W0 = (const float*)d_in[3];
    const float* enc_b0 = (const float*)d_in[4];
    const float* enc_W1 = (const float*)d_in[5];
    const float* enc_b1 = (const float*)d_in[6];
    const float* dec_W0 = (const float*)d_in[7];
    const float* dec_b0 = (const float*)d_in[8];
    const float* dec_W1 = (const float*)d_in[9];
    const float* dec_b1 = (const float*)d_in[10];
    const float* be_W0  = (const float*)d_in[11];
    const float* be_b0  = (const float*)d_in[12];
    const float* be_W1  = (const float*)d_in[13];
    const float* be_b1  = (const float*)d_in[14];
    const float* bd_W0  = (const float*)d_in[15];
    const float* bd_b0  = (const float*)d_in[16];
    const float* bd_W1  = (const float*)d_in[17];
    const float* bd_b1  = (const float*)d_in[18];
    const float* bil_W  = (const float*)d_in[19];
    const int*   edge   = (const int*)d_in[20];
    const int*   subidx = (const int*)d_in[21];
    const int*   pos    = (const int*)d_in[22];
    const int*   neg    = (const int*)d_in[23];

    const int* src = edge;
    const int* dst = edge + N_EDGES;

    static float *bufA=nullptr,*bufB,*bufC,*bufD,*bufE,*zn,*zn2,*be,*znb,*aggd;
    if (!bufA) {
        cudaGetSymbolAddress((void**)&bufA, g_bufA);
        cudaGetSymbolAddress((void**)&bufB, g_bufB);
        cudaGetSymbolAddress((void**)&bufC, g_bufC);
        cudaGetSymbolAddress((void**)&bufD, g_bufD);
        cudaGetSymbolAddress((void**)&bufE, g_bufE);
        cudaGetSymbolAddress((void**)&zn,   g_zn);
        cudaGetSymbolAddress((void**)&zn2,  g_zn2);
        cudaGetSymbolAddress((void**)&be,   g_be);
        cudaGetSymbolAddress((void**)&znb,  g_znb);
        cudaGetSymbolAddress((void**)&aggd, g_aggd);
    }

    float* out       = (float*)d_out;
    float* o_zsub    = out;
    float* o_zsubshf = out + (size_t)N_NODES * Z_DIM;
    float* o_recon   = out + 2ull * N_NODES * Z_DIM;
    float* o_lp      = o_recon + (size_t)N_NODES * IN_DIM;
    float* o_ln      = o_lp + P_PAIRS;
    float* o_lb      = o_ln + P_PAIRS;

    const dim3 gemm_blk(256);
    const int  MB = (N_NODES + BM - 1) / BM;  // 235

    // ---- encoder helper (inline twice) ----
    auto encode = [&](const float* xin, float* z_out, float* pool_out) {
        // layer 0: y = x @ W0 ; agg in H-space ; h = relu(LN(y + agg + b0))
        sgemm_kernel<<<dim3(H_DIM / BNT, MB), gemm_blk>>>(
            N_NODES, H_DIM, IN_DIM, xin, nullptr, enc_W0, nullptr, bufA);
        cudaMemsetAsync(bufB, 0, (size_t)N_NODES * H_DIM * sizeof(float), 0);
        {
            long long tot = (long long)N_EDGES * (H_DIM / 4);
            agg_kernel<H_DIM><<<(unsigned)((tot + 255) / 256), 256>>>(bufA, bufB, src, dst, N_EDGES);
        }
        ln_relu_kernel<H_DIM><<<(N_NODES * 32 + 255) / 256, 256>>>(bufA, bufB, enc_b0, bufC, N_NODES);

        // layer 1: y = h @ W1 ; agg in Z-space ; z = relu(LN(y + agg + b1))
        sgemm_kernel<<<dim3(Z_DIM / BNT, MB), gemm_blk>>>(
            N_NODES, Z_DIM, H_DIM, bufC, nullptr, enc_W1, nullptr, bufD);
        cudaMemsetAsync(bufE, 0, (size_t)N_NODES * Z_DIM * sizeof(float), 0);
        {
            long long tot = (long long)N_EDGES * (Z_DIM / 4);
            agg_kernel<Z_DIM><<<(unsigned)((tot + 255) / 256), 256>>>(bufD, bufE, src, dst, N_EDGES);
        }
        ln_relu_kernel<Z_DIM><<<(N_NODES * 32 + 255) / 256, 256>>>(bufD, bufE, enc_b1, z_out, N_NODES);

        // subgraph mean pool
        pool_kernel<<<(N_NODES * 32 + 255) / 256, 256>>>(z_out, subidx, pool_out, N_NODES);
    };

    encode(x,     zn,  o_zsub);
    encode(x_shf, zn2, o_zsubshf);

    // batch encoder MLP
    be_kernel<<<(N_NODES + 255) / 256, 256>>>(bl, be_W0, be_b0, be_W1, be_b1, be, N_NODES);

    // batch discriminator on z_sub
    bd_kernel<<<N_NODES, 64>>>(o_zsub, bd_W0, bd_b0, bd_W1, bd_b1, o_lb);

    // bilinear contrastive logits
    bil_kernel<<<P_PAIRS, 128>>>(o_zsub, o_zsubshf, bil_W, pos, neg, o_lp, o_ln);

    // decoder input: concat(z_node, batch_emb)
    concat_kernel<<<(N_NODES * DEC0_DIM + 255) / 256, 256>>>(zn, be, znb, N_NODES);

    // dec layer 0: agg in 144-space (input dim < output dim), then GEMM + LN + relu
    cudaMemsetAsync(aggd, 0, (size_t)N_NODES * DEC0_DIM * sizeof(float), 0);
    {
        long long tot = (long long)N_EDGES * (DEC0_DIM / 4);
        agg_kernel<DEC0_DIM><<<(unsigned)((tot + 255) / 256), 256>>>(znb, aggd, src, dst, N_EDGES);
    }
    sgemm_kernel<<<dim3(H_DIM / BNT, MB), gemm_blk>>>(
        N_NODES, H_DIM, DEC0_DIM, znb, aggd, dec_W0, nullptr, bufA);
    ln_relu_kernel<H_DIM><<<(N_NODES * 32 + 255) / 256, 256>>>(bufA, nullptr, dec_b0, bufC, N_NODES);

    // dec layer 1: agg in H-space (input dim < output dim), GEMM + bias -> recon
    cudaMemsetAsync(bufB, 0, (size_t)N_NODES * H_DIM * sizeof(float), 0);
    {
        long long tot = (long long)N_EDGES * (H_DIM / 4);
        agg_kernel<H_DIM><<<(unsigned)((tot + 255) / 256), 256>>>(bufC, bufB, src, dst, N_EDGES);
    }
    sgemm_kernel<<<dim3(IN_DIM / BNT, MB), gemm_blk>>>(
        N_NODES, IN_DIM, H_DIM, bufC, bufB, dec_W1, dec_b1, o_recon);
}

// round 2
// speedup vs baseline: 2.8698x; 2.8698x over previous
#include <cuda_runtime.h>
#include <cuda_bf16.h>
#include <stdint.h>

// Problem constants
#define N_NODES 30000
#define N_EDGES 480000
#define K_SUB   32
#define P_PAIRS 16384
#define IN_DIM  1024
#define H_DIM   512
#define Z_DIM   128
#define BN_DIM  8
#define DB_DIM  16
#define DEC0_DIM 144   // Z + DB

// ---------------- scratch (static device globals; no allocation) -------------
__device__ float g_bufA[(size_t)N_NODES * H_DIM];
__device__ float g_bufB[(size_t)N_NODES * H_DIM];
__device__ float g_bufC[(size_t)N_NODES * H_DIM];
__device__ float g_bufD[(size_t)N_NODES * Z_DIM];
__device__ float g_bufE[(size_t)N_NODES * Z_DIM];
__device__ float g_zn  [(size_t)N_NODES * Z_DIM];
__device__ float g_zn2 [(size_t)N_NODES * Z_DIM];
__device__ float g_be  [(size_t)N_NODES * DB_DIM];
__device__ float g_znb [(size_t)N_NODES * DEC0_DIM];
__device__ float g_aggd[(size_t)N_NODES * DEC0_DIM];

// =============================================================================
// TF32 tensor-core GEMM: C[M,N] = A[M,K] @ B[K,N] (+bias)
// Tiles: 128x128x32, 256 threads (8 warps, 2x4), warp tile 64x32.
// mma.sync.aligned.m16n8k8.row.col.f32.tf32.tf32.f32
// Requires N % 128 == 0, K % 16 == 0, rows 16B-aligned.
// =============================================================================
#define GBM 128
#define GBN 128
#define GBK 32
#define ASTRIDE 36    // 128x36 floats per A buffer (pad 4 -> conflict-free frag LDS)
#define BSTRIDE 136   // 32x136 floats per B buffer (pad 8 -> conflict-free frag LDS)
#define GEMM_SMEM ((2*GBM*ASTRIDE + 2*GBK*BSTRIDE) * 4)   // 71680 bytes

__device__ __forceinline__ uint32_t f2tf32(float x) {
    uint32_t r;
    asm("cvt.rna.tf32.f32 %0, %1;" : "=r"(r) : "f"(x));
    return r;
}

__global__ __launch_bounds__(256, 2)
void mma_gemm_kernel(int M, int Nn, int K,
                     const float* __restrict__ A, const float* __restrict__ B,
                     const float* __restrict__ bias, float* __restrict__ C)
{
    extern __shared__ float smem[];
    float* AsBase = smem;                       // 2 * 128*36
    float* BsBase = smem + 2 * GBM * ASTRIDE;   // 2 * 32*136

    const int tid  = threadIdx.x;
    const int lane = tid & 31;
    const int wid  = tid >> 5;
    const int warpM = wid >> 2;      // 0..1
    const int warpN = wid & 3;       // 0..3
    const int grp   = lane >> 2;     // 0..7
    const int tig   = lane & 3;      // 0..3

    const int mBase = blockIdx.y * GBM;
    const int nBase = blockIdx.x * GBN;

    const int numStages = (K + GBK - 1) / GBK;   // >= 2 for all our shapes

    float acc[4][4][4];
    #pragma unroll
    for (int i = 0; i < 4; i++)
        #pragma unroll
        for (int j = 0; j < 4; j++)
            #pragma unroll
            for (int r = 0; r < 4; r++) acc[i][j][r] = 0.f;

    // ---- async stage loader ----
    auto loadStage = [&](int s, int buf) {
        float* Ab = AsBase + buf * GBM * ASTRIDE;
        float* Bb = BsBase + buf * GBK * BSTRIDE;
        const int k0 = s * GBK;
        #pragma unroll
        for (int i = 0; i < 4; i++) {
            int idx = tid + 256 * i;         // 0..1023
            int row = idx >> 3;              // 0..127
            int c4  = idx & 7;               // 0..7
            int m = mBase + row;
            int k = k0 + c4 * 4;
            const float* g = A + (size_t)m * K + k;
            uint32_t saddr = (uint32_t)__cvta_generic_to_shared(Ab + row * ASTRIDE + c4 * 4);
            int ssz = (m < M && k < K) ? 16 : 0;
            asm volatile("cp.async.cg.shared.global [%0], [%1], 16, %2;\n"
                         :: "r"(saddr), "l"(g), "r"(ssz));
        }
        #pragma unroll
        for (int i = 0; i < 4; i++) {
            int idx = tid + 256 * i;
            int kr  = idx >> 5;              // 0..31
            int c4  = idx & 31;              // 0..31
            int k = k0 + kr;
            const float* g = B + (size_t)k * Nn + nBase + c4 * 4;
            uint32_t saddr = (uint32_t)__cvta_generic_to_shared(Bb + kr * BSTRIDE + c4 * 4);
            int ssz = (k < K) ? 16 : 0;
            asm volatile("cp.async.cg.shared.global [%0], [%1], 16, %2;\n"
                         :: "r"(saddr), "l"(g), "r"(ssz));
        }
        asm volatile("cp.async.commit_group;\n");
    };

    loadStage(0, 0);
    loadStage(1, 1);
    asm volatile("cp.async.wait_group 1;\n");
    __syncthreads();

    for (int s = 0; s < numStages; s++) {
        const int buf = s & 1;
        const float* Ab = AsBase + buf * GBM * ASTRIDE;
        const float* Bb = BsBase + buf * GBK * BSTRIDE;

        #pragma unroll
        for (int kt = 0; kt < 4; kt++) {
            const int kb = kt * 8;
            uint32_t afr[4][4], bfr[4][2];
            #pragma unroll
            for (int ni = 0; ni < 4; ni++) {
                int n0 = warpN * 32 + ni * 8 + grp;
                int kk = kb + tig;
                bfr[ni][0] = f2tf32(Bb[kk * BSTRIDE + n0]);
                bfr[ni][1] = f2tf32(Bb[(kk + 4) * BSTRIDE + n0]);
            }
            #pragma unroll
            for (int mi = 0; mi < 4; mi++) {
                int r0 = warpM * 64 + mi * 16 + grp;
                int kk = kb + tig;
                afr[mi][0] = f2tf32(Ab[r0 * ASTRIDE + kk]);
                afr[mi][1] = f2tf32(Ab[(r0 + 8) * ASTRIDE + kk]);
                afr[mi][2] = f2tf32(Ab[r0 * ASTRIDE + kk + 4]);
                afr[mi][3] = f2tf32(Ab[(r0 + 8) * ASTRIDE + kk + 4]);
            }
            #pragma unroll
            for (int mi = 0; mi < 4; mi++)
                #pragma unroll
                for (int ni = 0; ni < 4; ni++) {
                    asm volatile(
                        "mma.sync.aligned.m16n8k8.row.col.f32.tf32.tf32.f32 "
                        "{%0,%1,%2,%3}, {%4,%5,%6,%7}, {%8,%9}, {%0,%1,%2,%3};\n"
                        : "+f"(acc[mi][ni][0]), "+f"(acc[mi][ni][1]),
                          "+f"(acc[mi][ni][2]), "+f"(acc[mi][ni][3])
                        : "r"(afr[mi][0]), "r"(afr[mi][1]), "r"(afr[mi][2]), "r"(afr[mi][3]),
                          "r"(bfr[ni][0]), "r"(bfr[ni][1]));
                }
        }

        if (s + 1 < numStages) {
            if (s + 2 < numStages) {
                __syncthreads();                 // everyone done reading buf before overwrite
                loadStage(s + 2, buf);
                asm volatile("cp.async.wait_group 1;\n");
            } else {
                asm volatile("cp.async.wait_group 0;\n");
            }
            __syncthreads();
        }
    }

    // ---- epilogue ----
    #pragma unroll
    for (int mi = 0; mi < 4; mi++) {
        #pragma unroll
        for (int half = 0; half < 2; half++) {
            int m = mBase + warpM * 64 + mi * 16 + grp + half * 8;
            if (m < M) {
                #pragma unroll
                for (int ni = 0; ni < 4; ni++) {
                    int n = nBase + warpN * 32 + ni * 8 + 2 * tig;
                    float2 v = make_float2(acc[mi][ni][half * 2], acc[mi][ni][half * 2 + 1]);
                    if (bias) { v.x += bias[n]; v.y += bias[n + 1]; }
                    *(float2*)(C + (size_t)m * Nn + n) = v;
                }
            }
        }
    }
}

// ---------------- edge aggregation: out[dst] += X[src] (vector red) ----------
template<int D>
__global__ void agg_kernel(const float* __restrict__ X, float* __restrict__ out,
                           const int* __restrict__ src, const int* __restrict__ dst,
                           int E)
{
    constexpr int D4 = D / 4;
    long long idx = (long long)blockIdx.x * blockDim.x + threadIdx.x;
    if (idx >= (long long)E * D4) return;
    int e = (int)(idx / D4);
    int c = (int)(idx % D4) * 4;
    int s = __ldg(&src[e]);
    int d = __ldg(&dst[e]);
    float4 v = *(const float4*)(X + (size_t)s * D + c);
    float* o = out + (size_t)d * D + c;
    asm volatile("red.global.add.v4.f32 [%0], {%1,%2,%3,%4};\n"
                 :: "l"(o), "f"(v.x), "f"(v.y), "f"(v.z), "f"(v.w) : "memory");
}

// ---------------- fused (Y + bias) -> LayerNorm -> ReLU ----------------------
template<int D>
__global__ void ln_relu_kernel(const float* __restrict__ Y, const float* __restrict__ bias,
                               float* __restrict__ out, int Nrows)
{
    constexpr int V = D / 128;
    int w = (int)((blockIdx.x * (long long)blockDim.x + threadIdx.x) >> 5);
    if (w >= Nrows) return;
    int lane = threadIdx.x & 31;

    float4 v[V];
    float s = 0.f, sq = 0.f;
    #pragma unroll
    for (int i = 0; i < V; i++) {
        int c = (lane + i * 32) * 4;
        float4 y = *(const float4*)(Y + (size_t)w * D + c);
        float4 b = *(const float4*)(bias + c);
        y.x += b.x; y.y += b.y; y.z += b.z; y.w += b.w;
        v[i] = y;
        s  += y.x + y.y + y.z + y.w;
        sq += y.x*y.x + y.y*y.y + y.z*y.z + y.w*y.w;
    }
    #pragma unroll
    for (int off = 16; off; off >>= 1) {
        s  += __shfl_xor_sync(0xffffffffu, s,  off);
        sq += __shfl_xor_sync(0xffffffffu, sq, off);
    }
    float mean = s / D;
    float var  = sq / D - mean * mean;
    float inv  = rsqrtf(var + 1e-5f);
    #pragma unroll
    for (int i = 0; i < V; i++) {
        int c = (lane + i * 32) * 4;
        float4 y = v[i];
        y.x = fmaxf((y.x - mean) * inv, 0.f);
        y.y = fmaxf((y.y - mean) * inv, 0.f);
        y.z = fmaxf((y.z - mean) * inv, 0.f);
        y.w = fmaxf((y.w - mean) * inv, 0.f);
        *(float4*)(out + (size_t)w * D + c) = y;
    }
}

// ---------------- subgraph mean pool (K=32, Z=128): warp per node ------------
__global__ void pool_kernel(const float* __restrict__ zn, const int* __restrict__ idx,
                            float* __restrict__ out, int Nrows)
{
    int w = (int)((blockIdx.x * (long long)blockDim.x + threadIdx.x) >> 5);
    if (w >= Nrows) return;
    int lane = threadIdx.x & 31;
    int myidx = __ldg(&idx[(size_t)w * 32 + lane]);
    float4 acc = make_float4(0.f, 0.f, 0.f, 0.f);
    #pragma unroll
    for (int k = 0; k < 32; k++) {
        int j = __shfl_sync(0xffffffffu, myidx, k);
        float4 v = *(const float4*)(zn + (size_t)j * 128 + lane * 4);
        acc.x += v.x; acc.y += v.y; acc.z += v.z; acc.w += v.w;
    }
    const float inv = 1.f / 32.f;
    acc.x *= inv; acc.y *= inv; acc.z *= inv; acc.w *= inv;
    *(float4*)(out + (size_t)w * 128 + lane * 4) = acc;
}

// ---------------- batch encoder MLP (8 -> 12 relu -> 16) ---------------------
__global__ void be_kernel(const float* __restrict__ bl,
                          const float* __restrict__ W0, const float* __restrict__ b0,
                          const float* __restrict__ W1, const float* __restrict__ b1,
                          float* __restrict__ out, int Nr)
{
    int n = blockIdx.x * blockDim.x + threadIdx.x;
    if (n >= Nr) return;
    float in[8];
    #pragma unroll
    for (int i = 0; i < 8; i++) in[i] = bl[(size_t)n * 8 + i];
    float h[12];
    #pragma unroll
    for (int j = 0; j < 12; j++) {
        float s = b0[j];
        #pragma unroll
        for (int i = 0; i < 8; i++) s += in[i] * W0[i * 12 + j];
        h[j] = fmaxf(s, 0.f);
    }
    #pragma unroll
    for (int j = 0; j < 16; j++) {
        float s = b1[j];
        #pragma unroll
        for (int i = 0; i < 12; i++) s += h[i] * W1[i * 16 + j];
        out[(size_t)n * 16 + j] = s;
    }
}

// ---------------- batch discriminator (z_sub: 128 -> 64 relu -> 8) -----------
__global__ void bd_kernel(const float* __restrict__ zs,
                          const float* __restrict__ W0, const float* __restrict__ b0,
                          const float* __restrict__ W1, const float* __restrict__ b1,
                          float* __restrict__ out)
{
    int n = blockIdx.x;
    int t = threadIdx.x;  // 64
    __shared__ float z[128];
    __shared__ float h[64];
    z[t]      = zs[(size_t)n * 128 + t];
    z[64 + t] = zs[(size_t)n * 128 + 64 + t];
    __syncthreads();
    float s = b0[t];
    #pragma unroll 8
    for (int d = 0; d < 128; d++) s += z[d] * W0[d * 64 + t];
    h[t] = fmaxf(s, 0.f);
    __syncthreads();
    if (t < 8) {
        float o = b1[t];
        #pragma unroll 8
        for (int k = 0; k < 64; k++) o += h[k] * W1[k * 8 + t];
        out[(size_t)n * 8 + t] = o;
    }
}

// ---------------- bilinear discriminator -------------------------------------
__global__ void bil_kernel(const float* __restrict__ zs, const float* __restrict__ zss,
                           const float* __restrict__ W,
                           const int* __restrict__ pos, const int* __restrict__ neg,
                           float* __restrict__ lp, float* __restrict__ ln_)
{
    int p = blockIdx.x;
    int t = threadIdx.x;  // 128
    __shared__ float zp[128];
    __shared__ float red[8];
    int pi = __ldg(&pos[p]);
    int ni = __ldg(&neg[p]);
    zp[t] = zs[(size_t)pi * 128 + t];
    __syncthreads();
    float acc = 0.f;
    #pragma unroll 8
    for (int d = 0; d < 128; d++) acc += zp[d] * W[d * 128 + t];
    float sp = acc * zss[(size_t)pi * 128 + t];
    float sn = acc * zss[(size_t)ni * 128 + t];
    #pragma unroll
    for (int off = 16; off; off >>= 1) {
        sp += __shfl_xor_sync(0xffffffffu, sp, off);
        sn += __shfl_xor_sync(0xffffffffu, sn, off);
    }
    if ((t & 31) == 0) { red[t >> 5] = sp; red[4 + (t >> 5)] = sn; }
    __syncthreads();
    if (t == 0) lp[p]  = red[0] + red[1] + red[2] + red[3];
    if (t == 1) ln_[p] = red[4] + red[5] + red[6] + red[7];
}

// ---------------- concat z_node | batch_emb -> [N, 144] ----------------------
__global__ void concat_kernel(const float* __restrict__ zn, const float* __restrict__ be,
                              float* __restrict__ znb, int Nr)
{
    int idx = blockIdx.x * blockDim.x + threadIdx.x;
    if (idx >= Nr * DEC0_DIM) return;
    int n = idx / DEC0_DIM, c = idx - n * DEC0_DIM;
    znb[idx] = (c < Z_DIM) ? zn[(size_t)n * Z_DIM + c]
                           : be[(size_t)n * DB_DIM + (c - Z_DIM)];
}

// =============================================================================
extern "C" void kernel_launch(void* const* d_in, const int* in_sizes, int n_in,
                              void* d_out, int out_size)
{
    const float* x      = (const float*)d_in[0];
    const float* x_shf  = (const float*)d_in[1];
    const float* bl     = (const float*)d_in[2];
    const float* enc_W0 = (const float*)d_in[3];
    const float* enc_b0 = (const float*)d_in[4];
    const float* enc_W1 = (const float*)d_in[5];
    const float* enc_b1 = (const float*)d_in[6];
    const float* dec_W0 = (const float*)d_in[7];
    const float* dec_b0 = (const float*)d_in[8];
    const float* dec_W1 = (const float*)d_in[9];
    const float* dec_b1 = (const float*)d_in[10];
    const float* be_W0  = (const float*)d_in[11];
    const float* be_b0  = (const float*)d_in[12];
    const float* be_W1  = (const float*)d_in[13];
    const float* be_b1  = (const float*)d_in[14];
    const float* bd_W0  = (const float*)d_in[15];
    const float* bd_b0  = (const float*)d_in[16];
    const float* bd_W1  = (const float*)d_in[17];
    const float* bd_b1  = (const float*)d_in[18];
    const float* bil_W  = (const float*)d_in[19];
    const int*   edge   = (const int*)d_in[20];
    const int*   subidx = (const int*)d_in[21];
    const int*   pos    = (const int*)d_in[22];
    const int*   neg    = (const int*)d_in[23];

    const int* src = edge;
    const int* dst = edge + N_EDGES;

    static float *bufA=nullptr,*bufB,*bufC,*bufD,*bufE,*zn,*zn2,*be,*znb,*aggd;
    static bool attr_done = false;
    if (!bufA) {
        cudaGetSymbolAddress((void**)&bufA, g_bufA);
        cudaGetSymbolAddress((void**)&bufB, g_bufB);
        cudaGetSymbolAddress((void**)&bufC, g_bufC);
        cudaGetSymbolAddress((void**)&bufD, g_bufD);
        cudaGetSymbolAddress((void**)&bufE, g_bufE);
        cudaGetSymbolAddress((void**)&zn,   g_zn);
        cudaGetSymbolAddress((void**)&zn2,  g_zn2);
        cudaGetSymbolAddress((void**)&be,   g_be);
        cudaGetSymbolAddress((void**)&znb,  g_znb);
        cudaGetSymbolAddress((void**)&aggd, g_aggd);
    }
    if (!attr_done) {
        cudaFuncSetAttribute(mma_gemm_kernel,
                             cudaFuncAttributeMaxDynamicSharedMemorySize, GEMM_SMEM);
        attr_done = true;
    }

    float* out       = (float*)d_out;
    float* o_zsub    = out;
    float* o_zsubshf = out + (size_t)N_NODES * Z_DIM;
    float* o_recon   = out + 2ull * N_NODES * Z_DIM;
    float* o_lp      = o_recon + (size_t)N_NODES * IN_DIM;
    float* o_ln      = o_lp + P_PAIRS;
    float* o_lb      = o_ln + P_PAIRS;

    const int MB = (N_NODES + GBM - 1) / GBM;  // 235

    auto gemm = [&](int M, int Nn, int K, const float* A, const float* B,
                    const float* bias, float* C) {
        dim3 grid(Nn / GBN, MB);
        mma_gemm_kernel<<<grid, 256, GEMM_SMEM>>>(M, Nn, K, A, B, bias, C);
    };

    // ---- encoder (x 2 paths) ----
    auto encode = [&](const float* xin, float* z_out, float* pool_out) {
        // layer 0: y = x @ W0 ; agg in H-space (y + sum_nb y) ; relu(LN(+b0))
        gemm(N_NODES, H_DIM, IN_DIM, xin, enc_W0, nullptr, bufA);
        cudaMemcpyAsync(bufB, bufA, (size_t)N_NODES * H_DIM * sizeof(float),
                        cudaMemcpyDeviceToDevice, 0);
        {
            long long tot = (long long)N_EDGES * (H_DIM / 4);
            agg_kernel<H_DIM><<<(unsigned)((tot + 255) / 256), 256>>>(bufA, bufB, src, dst, N_EDGES);
        }
        ln_relu_kernel<H_DIM><<<(N_NODES * 32 + 255) / 256, 256>>>(bufB, enc_b0, bufC, N_NODES);

        // layer 1
        gemm(N_NODES, Z_DIM, H_DIM, bufC, enc_W1, nullptr, bufD);
        cudaMemcpyAsync(bufE, bufD, (size_t)N_NODES * Z_DIM * sizeof(float),
                        cudaMemcpyDeviceToDevice, 0);
        {
            long long tot = (long long)N_EDGES * (Z_DIM / 4);
            agg_kernel<Z_DIM><<<(unsigned)((tot + 255) / 256), 256>>>(bufD, bufE, src, dst, N_EDGES);
        }
        ln_relu_kernel<Z_DIM><<<(N_NODES * 32 + 255) / 256, 256>>>(bufE, enc_b1, z_out, N_NODES);

        pool_kernel<<<(N_NODES * 32 + 255) / 256, 256>>>(z_out, subidx, pool_out, N_NODES);
    };

    encode(x,     zn,  o_zsub);
    encode(x_shf, zn2, o_zsubshf);

    // batch encoder MLP
    be_kernel<<<(N_NODES + 255) / 256, 256>>>(bl, be_W0, be_b0, be_W1, be_b1, be, N_NODES);

    // batch discriminator on z_sub
    bd_kernel<<<N_NODES, 64>>>(o_zsub, bd_W0, bd_b0, bd_W1, bd_b1, o_lb);

    // bilinear contrastive logits
    bil_kernel<<<P_PAIRS, 128>>>(o_zsub, o_zsubshf, bil_W, pos, neg, o_lp, o_ln);

    // decoder input: concat(z_node, batch_emb)
    concat_kernel<<<(N_NODES * DEC0_DIM + 255) / 256, 256>>>(zn, be, znb, N_NODES);

    // dec layer 0: aggregate in 144-space first (self + neighbors), then GEMM + LN + relu
    cudaMemcpyAsync(aggd, znb, (size_t)N_NODES * DEC0_DIM * sizeof(float),
                    cudaMemcpyDeviceToDevice, 0);
    {
        long long tot = (long long)N_EDGES * (DEC0_DIM / 4);
        agg_kernel<DEC0_DIM><<<(unsigned)((tot + 255) / 256), 256>>>(znb, aggd, src, dst, N_EDGES);
    }
    gemm(N_NODES, H_DIM, DEC0_DIM, aggd, dec_W0, nullptr, bufA);
    ln_relu_kernel<H_DIM><<<(N_NODES * 32 + 255) / 256, 256>>>(bufA, dec_b0, bufC, N_NODES);

    // dec layer 1: aggregate in H-space, GEMM + bias -> recon
    cudaMemcpyAsync(bufB, bufC, (size_t)N_NODES * H_DIM * sizeof(float),
                    cudaMemcpyDeviceToDevice, 0);
    {
        long long tot = (long long)N_EDGES * (H_DIM / 4);
        agg_kernel<H_DIM><<<(unsigned)((tot + 255) / 256), 256>>>(bufC, bufB, src, dst, N_EDGES);
    }
    gemm(N_NODES, IN_DIM, H_DIM, bufB, dec_W1, dec_b1, o_recon);
}

// round 3
// speedup vs baseline: 4.2258x; 1.4725x over previous
#include <cuda_runtime.h>
#include <cuda_bf16.h>
#include <stdint.h>

// Problem constants
#define N_NODES 30000
#define N_EDGES 480000
#define K_SUB   32
#define P_PAIRS 16384
#define IN_DIM  1024
#define H_DIM   512
#define Z_DIM   128
#define BN_DIM  8
#define DB_DIM  16
#define DEC0_DIM 144   // Z + DB

// ---------------- scratch (static device globals; no allocation) -------------
__device__ float g_bufA[(size_t)N_NODES * H_DIM];
__device__ float g_bufB[(size_t)N_NODES * H_DIM];
__device__ float g_bufC[(size_t)N_NODES * H_DIM];
__device__ float g_bufD[(size_t)N_NODES * Z_DIM];
__device__ float g_zn  [(size_t)N_NODES * Z_DIM];
__device__ float g_zn2 [(size_t)N_NODES * Z_DIM];
__device__ float g_be  [(size_t)N_NODES * DB_DIM];
__device__ float g_znb [(size_t)N_NODES * DEC0_DIM];
__device__ float g_aggd[(size_t)N_NODES * DEC0_DIM];
__device__ int   g_cnt   [N_NODES];
__device__ int   g_start [N_NODES];
__device__ int   g_cursor[N_NODES];
__device__ int   g_csr   [N_EDGES];

// =============================================================================
// TF32 tensor-core GEMM: C[M,N] = A[M,K] @ B[K,N] (+bias)
// =============================================================================
#define GBM 128
#define GBN 128
#define GBK 32
#define ASTRIDE 36
#define BSTRIDE 136
#define GEMM_SMEM ((2*GBM*ASTRIDE + 2*GBK*BSTRIDE) * 4)

__device__ __forceinline__ uint32_t f2tf32(float x) {
    uint32_t r;
    asm("cvt.rna.tf32.f32 %0, %1;" : "=r"(r) : "f"(x));
    return r;
}

__global__ __launch_bounds__(256, 2)
void mma_gemm_kernel(int M, int Nn, int K,
                     const float* __restrict__ A, const float* __restrict__ B,
                     const float* __restrict__ bias, float* __restrict__ C)
{
    extern __shared__ float smem[];
    float* AsBase = smem;
    float* BsBase = smem + 2 * GBM * ASTRIDE;

    const int tid  = threadIdx.x;
    const int lane = tid & 31;
    const int wid  = tid >> 5;
    const int warpM = wid >> 2;
    const int warpN = wid & 3;
    const int grp   = lane >> 2;
    const int tig   = lane & 3;

    const int mBase = blockIdx.y * GBM;
    const int nBase = blockIdx.x * GBN;
    const int numStages = (K + GBK - 1) / GBK;

    float acc[4][4][4];
    #pragma unroll
    for (int i = 0; i < 4; i++)
        #pragma unroll
        for (int j = 0; j < 4; j++)
            #pragma unroll
            for (int r = 0; r < 4; r++) acc[i][j][r] = 0.f;

    auto loadStage = [&](int s, int buf) {
        float* Ab = AsBase + buf * GBM * ASTRIDE;
        float* Bb = BsBase + buf * GBK * BSTRIDE;
        const int k0 = s * GBK;
        #pragma unroll
        for (int i = 0; i < 4; i++) {
            int idx = tid + 256 * i;
            int row = idx >> 3;
            int c4  = idx & 7;
            int m = mBase + row;
            int k = k0 + c4 * 4;
            const float* g = A + (size_t)m * K + k;
            uint32_t saddr = (uint32_t)__cvta_generic_to_shared(Ab + row * ASTRIDE + c4 * 4);
            int ssz = (m < M && k < K) ? 16 : 0;
            asm volatile("cp.async.cg.shared.global [%0], [%1], 16, %2;\n"
                         :: "r"(saddr), "l"(g), "r"(ssz));
        }
        #pragma unroll
        for (int i = 0; i < 4; i++) {
            int idx = tid + 256 * i;
            int kr  = idx >> 5;
            int c4  = idx & 31;
            int k = k0 + kr;
            const float* g = B + (size_t)k * Nn + nBase + c4 * 4;
            uint32_t saddr = (uint32_t)__cvta_generic_to_shared(Bb + kr * BSTRIDE + c4 * 4);
            int ssz = (k < K) ? 16 : 0;
            asm volatile("cp.async.cg.shared.global [%0], [%1], 16, %2;\n"
                         :: "r"(saddr), "l"(g), "r"(ssz));
        }
        asm volatile("cp.async.commit_group;\n");
    };

    loadStage(0, 0);
    loadStage(1, 1);
    asm volatile("cp.async.wait_group 1;\n");
    __syncthreads();

    for (int s = 0; s < numStages; s++) {
        const int buf = s & 1;
        const float* Ab = AsBase + buf * GBM * ASTRIDE;
        const float* Bb = BsBase + buf * GBK * BSTRIDE;

        #pragma unroll
        for (int kt = 0; kt < 4; kt++) {
            const int kb = kt * 8;
            uint32_t afr[4][4], bfr[4][2];
            #pragma unroll
            for (int ni = 0; ni < 4; ni++) {
                int n0 = warpN * 32 + ni * 8 + grp;
                int kk = kb + tig;
                bfr[ni][0] = f2tf32(Bb[kk * BSTRIDE + n0]);
                bfr[ni][1] = f2tf32(Bb[(kk + 4) * BSTRIDE + n0]);
            }
            #pragma unroll
            for (int mi = 0; mi < 4; mi++) {
                int r0 = warpM * 64 + mi * 16 + grp;
                int kk = kb + tig;
                afr[mi][0] = f2tf32(Ab[r0 * ASTRIDE + kk]);
                afr[mi][1] = f2tf32(Ab[(r0 + 8) * ASTRIDE + kk]);
                afr[mi][2] = f2tf32(Ab[r0 * ASTRIDE + kk + 4]);
                afr[mi][3] = f2tf32(Ab[(r0 + 8) * ASTRIDE + kk + 4]);
            }
            #pragma unroll
            for (int mi = 0; mi < 4; mi++)
                #pragma unroll
                for (int ni = 0; ni < 4; ni++) {
                    asm volatile(
                        "mma.sync.aligned.m16n8k8.row.col.f32.tf32.tf32.f32 "
                        "{%0,%1,%2,%3}, {%4,%5,%6,%7}, {%8,%9}, {%0,%1,%2,%3};\n"
                        : "+f"(acc[mi][ni][0]), "+f"(acc[mi][ni][1]),
                          "+f"(acc[mi][ni][2]), "+f"(acc[mi][ni][3])
                        : "r"(afr[mi][0]), "r"(afr[mi][1]), "r"(afr[mi][2]), "r"(afr[mi][3]),
                          "r"(bfr[ni][0]), "r"(bfr[ni][1]));
                }
        }

        if (s + 1 < numStages) {
            if (s + 2 < numStages) {
                __syncthreads();
                loadStage(s + 2, buf);
                asm volatile("cp.async.wait_group 1;\n");
            } else {
                asm volatile("cp.async.wait_group 0;\n");
            }
            __syncthreads();
        }
    }

    #pragma unroll
    for (int mi = 0; mi < 4; mi++) {
        #pragma unroll
        for (int half = 0; half < 2; half++) {
            int m = mBase + warpM * 64 + mi * 16 + grp + half * 8;
            if (m < M) {
                #pragma unroll
                for (int ni = 0; ni < 4; ni++) {
                    int n = nBase + warpN * 32 + ni * 8 + 2 * tig;
                    float2 v = make_float2(acc[mi][ni][half * 2], acc[mi][ni][half * 2 + 1]);
                    if (bias) { v.x += bias[n]; v.y += bias[n + 1]; }
                    *(float2*)(C + (size_t)m * Nn + n) = v;
                }
            }
        }
    }
}

// =============================================================================
// CSR construction (by dst)
// =============================================================================
__global__ void hist_kernel(const int* __restrict__ dst, int* __restrict__ cnt, int E)
{
    int e = blockIdx.x * blockDim.x + threadIdx.x;
    if (e < E) atomicAdd(&cnt[dst[e]], 1);
}

__global__ void scan_kernel(const int* __restrict__ cnt, int* __restrict__ start,
                            int* __restrict__ cursor, int n)
{
    __shared__ int sums[1024];
    __shared__ int carry_s;
    if (threadIdx.x == 0) carry_s = 0;
    __syncthreads();
    for (int base = 0; base < n; base += 1024) {
        int i = base + threadIdx.x;
        int v = (i < n) ? cnt[i] : 0;
        sums[threadIdx.x] = v;
        __syncthreads();
        #pragma unroll
        for (int off = 1; off < 1024; off <<= 1) {
            int t = (threadIdx.x >= off) ? sums[threadIdx.x - off] : 0;
            __syncthreads();
            sums[threadIdx.x] += t;
            __syncthreads();
        }
        int excl = carry_s + sums[threadIdx.x] - v;
        if (i < n) { start[i] = excl; cursor[i] = excl; }
        __syncthreads();
        if (threadIdx.x == 1023) carry_s = excl + v;
        __syncthreads();
    }
}

__global__ void scatter_kernel(const int* __restrict__ src, const int* __restrict__ dst,
                               int* __restrict__ cursor, int* __restrict__ csr, int E)
{
    int e = blockIdx.x * blockDim.x + threadIdx.x;
    if (e >= E) return;
    int pos = atomicAdd(&cursor[dst[e]], 1);
    csr[pos] = src[e];
}

// =============================================================================
// Fused GIN aggregation: out[i] = f( X[i] + sum_{j in N(i)} X[j] [+bias] )
// f = LN+ReLU if LNR, identity otherwise. Warp per node.
// =============================================================================
template<int D, bool LNR>
__global__ void gin_agg_kernel(const float* __restrict__ X,
                               const int* __restrict__ start, const int* __restrict__ cnt,
                               const int* __restrict__ csr,
                               const float* __restrict__ bias,
                               float* __restrict__ out, int Nrows)
{
    constexpr int C4 = D / 4;             // float4 per row
    constexpr int V  = (C4 + 31) / 32;    // float4 per lane
    int w = (int)((blockIdx.x * (long long)blockDim.x + threadIdx.x) >> 5);
    if (w >= Nrows) return;
    int lane = threadIdx.x & 31;

    float4 acc[V];
    #pragma unroll
    for (int v = 0; v < V; v++) {
        int c4 = lane + v * 32;
        if (c4 < C4) acc[v] = *(const float4*)(X + (size_t)w * D + c4 * 4);
        else         acc[v] = make_float4(0.f, 0.f, 0.f, 0.f);
    }

    int s0  = start[w];
    int deg = cnt[w];
    for (int base = 0; base < deg; base += 32) {
        int rem = deg - base;
        int myid = (lane < rem) ? csr[s0 + base + lane] : 0;
        int m = rem < 32 ? rem : 32;
        for (int k = 0; k < m; k++) {
            int j = __shfl_sync(0xffffffffu, myid, k);
            const float* row = X + (size_t)j * D;
            #pragma unroll
            for (int v = 0; v < V; v++) {
                int c4 = lane + v * 32;
                if (c4 < C4) {
                    float4 t = *(const float4*)(row + c4 * 4);
                    acc[v].x += t.x; acc[v].y += t.y; acc[v].z += t.z; acc[v].w += t.w;
                }
            }
        }
    }

    if (LNR) {
        float s = 0.f, sq = 0.f;
        #pragma unroll
        for (int v = 0; v < V; v++) {
            int c4 = lane + v * 32;
            if (c4 < C4) {
                float4 b = *(const float4*)(bias + c4 * 4);
                acc[v].x += b.x; acc[v].y += b.y; acc[v].z += b.z; acc[v].w += b.w;
                s  += acc[v].x + acc[v].y + acc[v].z + acc[v].w;
                sq += acc[v].x*acc[v].x + acc[v].y*acc[v].y
                    + acc[v].z*acc[v].z + acc[v].w*acc[v].w;
            }
        }
        #pragma unroll
        for (int off = 16; off; off >>= 1) {
            s  += __shfl_xor_sync(0xffffffffu, s,  off);
            sq += __shfl_xor_sync(0xffffffffu, sq, off);
        }
        float mean = s / D;
        float var  = sq / D - mean * mean;
        float inv  = rsqrtf(var + 1e-5f);
        #pragma unroll
        for (int v = 0; v < V; v++) {
            acc[v].x = fmaxf((acc[v].x - mean) * inv, 0.f);
            acc[v].y = fmaxf((acc[v].y - mean) * inv, 0.f);
            acc[v].z = fmaxf((acc[v].z - mean) * inv, 0.f);
            acc[v].w = fmaxf((acc[v].w - mean) * inv, 0.f);
        }
    }

    #pragma unroll
    for (int v = 0; v < V; v++) {
        int c4 = lane + v * 32;
        if (c4 < C4) *(float4*)(out + (size_t)w * D + c4 * 4) = acc[v];
    }
}

// ---------------- fused (Y + bias) -> LayerNorm -> ReLU ----------------------
template<int D>
__global__ void ln_relu_kernel(const float* __restrict__ Y, const float* __restrict__ bias,
                               float* __restrict__ out, int Nrows)
{
    constexpr int V = D / 128;
    int w = (int)((blockIdx.x * (long long)blockDim.x + threadIdx.x) >> 5);
    if (w >= Nrows) return;
    int lane = threadIdx.x & 31;

    float4 v[V];
    float s = 0.f, sq = 0.f;
    #pragma unroll
    for (int i = 0; i < V; i++) {
        int c = (lane + i * 32) * 4;
        float4 y = *(const float4*)(Y + (size_t)w * D + c);
        float4 b = *(const float4*)(bias + c);
        y.x += b.x; y.y += b.y; y.z += b.z; y.w += b.w;
        v[i] = y;
        s  += y.x + y.y + y.z + y.w;
        sq += y.x*y.x + y.y*y.y + y.z*y.z + y.w*y.w;
    }
    #pragma unroll
    for (int off = 16; off; off >>= 1) {
        s  += __shfl_xor_sync(0xffffffffu, s,  off);
        sq += __shfl_xor_sync(0xffffffffu, sq, off);
    }
    float mean = s / D;
    float var  = sq / D - mean * mean;
    float inv  = rsqrtf(var + 1e-5f);
    #pragma unroll
    for (int i = 0; i < V; i++) {
        int c = (lane + i * 32) * 4;
        float4 y = v[i];
        y.x = fmaxf((y.x - mean) * inv, 0.f);
        y.y = fmaxf((y.y - mean) * inv, 0.f);
        y.z = fmaxf((y.z - mean) * inv, 0.f);
        y.w = fmaxf((y.w - mean) * inv, 0.f);
        *(float4*)(out + (size_t)w * D + c) = y;
    }
}

// ---------------- subgraph mean pool (K=32, Z=128): warp per node ------------
__global__ void pool_kernel(const float* __restrict__ zn, const int* __restrict__ idx,
                            float* __restrict__ out, int Nrows)
{
    int w = (int)((blockIdx.x * (long long)blockDim.x + threadIdx.x) >> 5);
    if (w >= Nrows) return;
    int lane = threadIdx.x & 31;
    int myidx = __ldg(&idx[(size_t)w * 32 + lane]);
    float4 acc = make_float4(0.f, 0.f, 0.f, 0.f);
    #pragma unroll
    for (int k = 0; k < 32; k++) {
        int j = __shfl_sync(0xffffffffu, myidx, k);
        float4 v = *(const float4*)(zn + (size_t)j * 128 + lane * 4);
        acc.x += v.x; acc.y += v.y; acc.z += v.z; acc.w += v.w;
    }
    const float inv = 1.f / 32.f;
    acc.x *= inv; acc.y *= inv; acc.z *= inv; acc.w *= inv;
    *(float4*)(out + (size_t)w * 128 + lane * 4) = acc;
}

// ---------------- batch encoder MLP (8 -> 12 relu -> 16) ---------------------
__global__ void be_kernel(const float* __restrict__ bl,
                          const float* __restrict__ W0, const float* __restrict__ b0,
                          const float* __restrict__ W1, const float* __restrict__ b1,
                          float* __restrict__ out, int Nr)
{
    int n = blockIdx.x * blockDim.x + threadIdx.x;
    if (n >= Nr) return;
    float in[8];
    #pragma unroll
    for (int i = 0; i < 8; i++) in[i] = bl[(size_t)n * 8 + i];
    float h[12];
    #pragma unroll
    for (int j = 0; j < 12; j++) {
        float s = b0[j];
        #pragma unroll
        for (int i = 0; i < 8; i++) s += in[i] * W0[i * 12 + j];
        h[j] = fmaxf(s, 0.f);
    }
    #pragma unroll
    for (int j = 0; j < 16; j++) {
        float s = b1[j];
        #pragma unroll
        for (int i = 0; i < 12; i++) s += h[i] * W1[i * 16 + j];
        out[(size_t)n * 16 + j] = s;
    }
}

// ---------------- batch discriminator (z_sub: 128 -> 64 relu -> 8) -----------
__global__ void bd_kernel(const float* __restrict__ zs,
                          const float* __restrict__ W0, const float* __restrict__ b0,
                          const float* __restrict__ W1, const float* __restrict__ b1,
                          float* __restrict__ out)
{
    int n = blockIdx.x;
    int t = threadIdx.x;  // 64
    __shared__ float z[128];
    __shared__ float h[64];
    z[t]      = zs[(size_t)n * 128 + t];
    z[64 + t] = zs[(size_t)n * 128 + 64 + t];
    __syncthreads();
    float s = b0[t];
    #pragma unroll 8
    for (int d = 0; d < 128; d++) s += z[d] * W0[d * 64 + t];
    h[t] = fmaxf(s, 0.f);
    __syncthreads();
    if (t < 8) {
        float o = b1[t];
        #pragma unroll 8
        for (int k = 0; k < 64; k++) o += h[k] * W1[k * 8 + t];
        out[(size_t)n * 8 + t] = o;
    }
}

// ---------------- bilinear discriminator -------------------------------------
__global__ void bil_kernel(const float* __restrict__ zs, const float* __restrict__ zss,
                           const float* __restrict__ W,
                           const int* __restrict__ pos, const int* __restrict__ neg,
                           float* __restrict__ lp, float* __restrict__ ln_)
{
    int p = blockIdx.x;
    int t = threadIdx.x;  // 128
    __shared__ float zp[128];
    __shared__ float red[8];
    int pi = __ldg(&pos[p]);
    int ni = __ldg(&neg[p]);
    zp[t] = zs[(size_t)pi * 128 + t];
    __syncthreads();
    float acc = 0.f;
    #pragma unroll 8
    for (int d = 0; d < 128; d++) acc += zp[d] * W[d * 128 + t];
    float sp = acc * zss[(size_t)pi * 128 + t];
    float sn = acc * zss[(size_t)ni * 128 + t];
    #pragma unroll
    for (int off = 16; off; off >>= 1) {
        sp += __shfl_xor_sync(0xffffffffu, sp, off);
        sn += __shfl_xor_sync(0xffffffffu, sn, off);
    }
    if ((t & 31) == 0) { red[t >> 5] = sp; red[4 + (t >> 5)] = sn; }
    __syncthreads();
    if (t == 0) lp[p]  = red[0] + red[1] + red[2] + red[3];
    if (t == 1) ln_[p] = red[4] + red[5] + red[6] + red[7];
}

// ---------------- concat z_node | batch_emb -> [N, 144] ----------------------
__global__ void concat_kernel(const float* __restrict__ zn, const float* __restrict__ be,
                              float* __restrict__ znb, int Nr)
{
    int idx = blockIdx.x * blockDim.x + threadIdx.x;
    if (idx >= Nr * DEC0_DIM) return;
    int n = idx / DEC0_DIM, c = idx - n * DEC0_DIM;
    znb[idx] = (c < Z_DIM) ? zn[(size_t)n * Z_DIM + c]
                           : be[(size_t)n * DB_DIM + (c - Z_DIM)];
}

// =============================================================================
extern "C" void kernel_launch(void* const* d_in, const int* in_sizes, int n_in,
                              void* d_out, int out_size)
{
    const float* x      = (const float*)d_in[0];
    const float* x_shf  = (const float*)d_in[1];
    const float* bl     = (const float*)d_in[2];
    const float* enc_W0 = (const float*)d_in[3];
    const float* enc_b0 = (const float*)d_in[4];
    const float* enc_W1 = (const float*)d_in[5];
    const float* enc_b1 = (const float*)d_in[6];
    const float* dec_W0 = (const float*)d_in[7];
    const float* dec_b0 = (const float*)d_in[8];
    const float* dec_W1 = (const float*)d_in[9];
    const float* dec_b1 = (const float*)d_in[10];
    const float* be_W0  = (const float*)d_in[11];
    const float* be_b0  = (const float*)d_in[12];
    const float* be_W1  = (const float*)d_in[13];
    const float* be_b1  = (const float*)d_in[14];
    const float* bd_W0  = (const float*)d_in[15];
    const float* bd_b0  = (const float*)d_in[16];
    const float* bd_W1  = (const float*)d_in[17];
    const float* bd_b1  = (const float*)d_in[18];
    const float* bil_W  = (const float*)d_in[19];
    const int*   edge   = (const int*)d_in[20];
    const int*   subidx = (const int*)d_in[21];
    const int*   pos    = (const int*)d_in[22];
    const int*   neg    = (const int*)d_in[23];

    const int* src = edge;
    const int* dst = edge + N_EDGES;

    static float *bufA=nullptr,*bufB,*bufC,*bufD,*zn,*zn2,*be,*znb,*aggd;
    static int *cnt,*startp,*cursor,*csr;
    static bool attr_done = false;
    if (!bufA) {
        cudaGetSymbolAddress((void**)&bufA, g_bufA);
        cudaGetSymbolAddress((void**)&bufB, g_bufB);
        cudaGetSymbolAddress((void**)&bufC, g_bufC);
        cudaGetSymbolAddress((void**)&bufD, g_bufD);
        cudaGetSymbolAddress((void**)&zn,   g_zn);
        cudaGetSymbolAddress((void**)&zn2,  g_zn2);
        cudaGetSymbolAddress((void**)&be,   g_be);
        cudaGetSymbolAddress((void**)&znb,  g_znb);
        cudaGetSymbolAddress((void**)&aggd, g_aggd);
        cudaGetSymbolAddress((void**)&cnt,    g_cnt);
        cudaGetSymbolAddress((void**)&startp, g_start);
        cudaGetSymbolAddress((void**)&cursor, g_cursor);
        cudaGetSymbolAddress((void**)&csr,    g_csr);
    }
    if (!attr_done) {
        cudaFuncSetAttribute(mma_gemm_kernel,
                             cudaFuncAttributeMaxDynamicSharedMemorySize, GEMM_SMEM);
        attr_done = true;
    }

    float* out       = (float*)d_out;
    float* o_zsub    = out;
    float* o_zsubshf = out + (size_t)N_NODES * Z_DIM;
    float* o_recon   = out + 2ull * N_NODES * Z_DIM;
    float* o_lp      = o_recon + (size_t)N_NODES * IN_DIM;
    float* o_ln      = o_lp + P_PAIRS;
    float* o_lb      = o_ln + P_PAIRS;

    const int MB = (N_NODES + GBM - 1) / GBM;

    auto gemm = [&](int M, int Nn, int K, const float* A, const float* B,
                    const float* bias, float* C) {
        dim3 grid(Nn / GBN, MB);
        mma_gemm_kernel<<<grid, 256, GEMM_SMEM>>>(M, Nn, K, A, B, bias, C);
    };

    // ---- CSR build (reused by all aggregations) ----
    cudaMemsetAsync(cnt, 0, N_NODES * sizeof(int), 0);
    hist_kernel<<<(N_EDGES + 255) / 256, 256>>>(dst, cnt, N_EDGES);
    scan_kernel<<<1, 1024>>>(cnt, startp, cursor, N_NODES);
    scatter_kernel<<<(N_EDGES + 255) / 256, 256>>>(src, dst, cursor, csr, N_EDGES);

    const int AGG_GRID = (N_NODES * 32 + 255) / 256;

    // ---- encoder (x 2 paths) ----
    auto encode = [&](const float* xin, float* z_out, float* pool_out) {
        // layer 0: y = x @ W0 ; fused self+agg+bias+LN+ReLU
        gemm(N_NODES, H_DIM, IN_DIM, xin, enc_W0, nullptr, bufA);
        gin_agg_kernel<H_DIM, true><<<AGG_GRID, 256>>>(bufA, startp, cnt, csr, enc_b0, bufC, N_NODES);

        // layer 1
        gemm(N_NODES, Z_DIM, H_DIM, bufC, enc_W1, nullptr, bufD);
        gin_agg_kernel<Z_DIM, true><<<AGG_GRID, 256>>>(bufD, startp, cnt, csr, enc_b1, z_out, N_NODES);

        pool_kernel<<<AGG_GRID, 256>>>(z_out, subidx, pool_out, N_NODES);
    };

    encode(x,     zn,  o_zsub);
    encode(x_shf, zn2, o_zsubshf);

    // batch encoder MLP
    be_kernel<<<(N_NODES + 255) / 256, 256>>>(bl, be_W0, be_b0, be_W1, be_b1, be, N_NODES);

    // batch discriminator on z_sub
    bd_kernel<<<N_NODES, 64>>>(o_zsub, bd_W0, bd_b0, bd_W1, bd_b1, o_lb);

    // bilinear contrastive logits
    bil_kernel<<<P_PAIRS, 128>>>(o_zsub, o_zsubshf, bil_W, pos, neg, o_lp, o_ln);

    // decoder input: concat(z_node, batch_emb)
    concat_kernel<<<(N_NODES * DEC0_DIM + 255) / 256, 256>>>(zn, be, znb, N_NODES);

    // dec layer 0: aggregate (self+neighbors) in 144-space, then GEMM + LN + relu
    gin_agg_kernel<DEC0_DIM, false><<<AGG_GRID, 256>>>(znb, startp, cnt, csr, nullptr, aggd, N_NODES);
    gemm(N_NODES, H_DIM, DEC0_DIM, aggd, dec_W0, nullptr, bufA);
    ln_relu_kernel<H_DIM><<<AGG_GRID, 256>>>(bufA, dec_b0, bufC, N_NODES);

    // dec layer 1: aggregate in H-space, GEMM + bias -> recon
    gin_agg_kernel<H_DIM, false><<<AGG_GRID, 256>>>(bufC, startp, cnt, csr, nullptr, bufB, N_NODES);
    gemm(N_NODES, IN_DIM, H_DIM, bufB, dec_W1, dec_b1, o_recon);
}